// round 12
// baseline (speedup 1.0000x reference)
#include <cuda_runtime.h>
#include <stdint.h>

#define N_POS 8192
#define N_NEG 4000u
#define N_TOT (N_POS + N_POS * (int)N_NEG)  // 32,776,192 (divisible by 4)
#define N_VEC (N_TOT / 4)                   // 8,194,048

#define HIST_WORDS (N_POS / 2)              // 4096 packed u16x2 words

#define P2_BLOCKS 296
#define P2_THREADS 1024

#define P3A_BLOCKS 32
#define P3A_THREADS 128                     // 32*128 = 4096 = one thread per word

// Scratch (allocation-free rule: __device__ globals)
__device__ float          g_pos[N_POS];
__device__ unsigned short g_rowid[N_TOT];                     // 65.55 MB
__device__ unsigned int   g_hist_all[P2_BLOCKS * HIST_WORDS]; // 4.85 MB, atomic-free
__device__ double         g_partial[P3A_BLOCKS];

// ---------------------------------------------------------------------------
// Pass 1: scan idx (int32) once. Emit u16 row-id per element (0xFFFF = pos),
// scatter the 8192 pos values. No histogram zeroing needed (overwrite flush).
// ---------------------------------------------------------------------------
__global__ void __launch_bounds__(256) mrr_pass1(
    const float* __restrict__ val, const int* __restrict__ idx)
{
    const unsigned int tid = blockIdx.x * blockDim.x + threadIdx.x;
    const unsigned int stride = gridDim.x * blockDim.x;

    const int4* __restrict__ idx4 = (const int4*)idx;
    ushort4* __restrict__ rid4 = (ushort4*)g_rowid;

    #pragma unroll 4
    for (unsigned int v = tid; v < N_VEC; v += stride) {
        int4 q = idx4[v];
        unsigned int j0 = (unsigned int)q.x;
        unsigned int j1 = (unsigned int)q.y;
        unsigned int j2 = (unsigned int)q.z;
        unsigned int j3 = (unsigned int)q.w;
        unsigned int base = v * 4u;

        ushort4 r;
        if (j0 < N_POS) { r.x = 0xFFFFu; g_pos[j0] = val[base + 0]; }
        else            { r.x = (unsigned short)((j0 - N_POS) / N_NEG); }
        if (j1 < N_POS) { r.y = 0xFFFFu; g_pos[j1] = val[base + 1]; }
        else            { r.y = (unsigned short)((j1 - N_POS) / N_NEG); }
        if (j2 < N_POS) { r.z = 0xFFFFu; g_pos[j2] = val[base + 2]; }
        else            { r.z = (unsigned short)((j2 - N_POS) / N_NEG); }
        if (j3 < N_POS) { r.w = 0xFFFFu; g_pos[j3] = val[base + 3]; }
        else            { r.w = (unsigned short)((j3 - N_POS) / N_NEG); }

        rid4[v] = r;
    }
}

// ---------------------------------------------------------------------------
// Pass 2: val4 + rowid4 streams, SMEM-privatized packed histogram with
// minority-side counting:
//   p >  0 -> count (v >  p);  p <= 0 -> count (v <= p)
// inc = (v > p) XOR (p <= 0); fixed up in pass 3. Per-row per-block count fits
// u16 trivially. Flush = plain coalesced STG of the block's 16KB histogram to
// its PRIVATE slice of g_hist_all -- zero atomics, zero serialization.
// 48KB static smem, 1024 threads -> 2 blocks/SM, 296 blocks = 1 wave.
// ---------------------------------------------------------------------------
__global__ void __launch_bounds__(P2_THREADS) mrr_pass2(const float* __restrict__ val)
{
    __shared__ float        s_pos[N_POS];       // 32768 B
    __shared__ unsigned int s_hist[HIST_WORDS]; // 16384 B

    const int t = threadIdx.x;
    for (int i = t; i < N_POS; i += P2_THREADS)      s_pos[i]  = g_pos[i];
    for (int i = t; i < HIST_WORDS; i += P2_THREADS) s_hist[i] = 0u;
    __syncthreads();

    const unsigned int tid = blockIdx.x * P2_THREADS + t;
    const unsigned int stride = gridDim.x * P2_THREADS;
    const float4*  __restrict__ v4 = (const float4*)val;
    const ushort4* __restrict__ r4 = (const ushort4*)g_rowid;

    #pragma unroll 2
    for (unsigned int v = tid; v < N_VEC; v += stride) {
        float4  f = v4[v];
        ushort4 r = r4[v];
        {
            float p = s_pos[r.x & 0x1FFFu];
            if (r.x != 0xFFFFu && ((f.x > p) != (p <= 0.0f)))
                atomicAdd(&s_hist[r.x >> 1], 1u << ((r.x & 1u) << 4));
        }
        {
            float p = s_pos[r.y & 0x1FFFu];
            if (r.y != 0xFFFFu && ((f.y > p) != (p <= 0.0f)))
                atomicAdd(&s_hist[r.y >> 1], 1u << ((r.y & 1u) << 4));
        }
        {
            float p = s_pos[r.z & 0x1FFFu];
            if (r.z != 0xFFFFu && ((f.z > p) != (p <= 0.0f)))
                atomicAdd(&s_hist[r.z >> 1], 1u << ((r.z & 1u) << 4));
        }
        {
            float p = s_pos[r.w & 0x1FFFu];
            if (r.w != 0xFFFFu && ((f.w > p) != (p <= 0.0f)))
                atomicAdd(&s_hist[r.w >> 1], 1u << ((r.w & 1u) << 4));
        }
    }
    __syncthreads();

    // Atomic-free flush: private coalesced store (16KB burst per block).
    unsigned int* __restrict__ dst = &g_hist_all[blockIdx.x * HIST_WORDS];
    for (int i = t; i < HIST_WORDS; i += P2_THREADS)
        dst[i] = s_hist[i];
}

// ---------------------------------------------------------------------------
// Pass 3a: one thread per packed word. Fixed-order sum across the 296 block
// histograms (warp reads 128B contiguous per block-iter -> coalesced), undo
// minority-side flip, write the two sample_mrr values, per-block double sum.
// ---------------------------------------------------------------------------
__global__ void __launch_bounds__(P3A_THREADS) mrr_pass3a(float* __restrict__ out)
{
    __shared__ double ssum[P3A_THREADS];
    const int t = threadIdx.x;
    const int w = blockIdx.x * P3A_THREADS + t;   // packed word = rows 2w, 2w+1

    unsigned int acc = 0u;
    #pragma unroll 4
    for (int b = 0; b < P2_BLOCKS; b++)
        acc += g_hist_all[b * HIST_WORDS + w];    // halves can't carry (<=4000)

    unsigned int c0 = acc & 0xFFFFu;
    unsigned int c1 = acc >> 16;
    float p0 = g_pos[2 * w];
    float p1 = g_pos[2 * w + 1];
    unsigned int g0 = (p0 > 0.0f) ? c0 : (N_NEG - c0);
    unsigned int g1 = (p1 > 0.0f) ? c1 : (N_NEG - c1);
    float s0 = 1.0f / (float)(1u + g0);
    float s1 = 1.0f / (float)(1u + g1);
    // out+1 is only 4B-aligned: scalar stores (no vector STG.64 on odd offset)
    out[1 + 2 * w]     = s0;
    out[1 + 2 * w + 1] = s1;

    ssum[t] = (double)s0 + (double)s1;
    __syncthreads();
    for (int off = P3A_THREADS / 2; off > 0; off >>= 1) {
        if (t < off) ssum[t] += ssum[t + off];
        __syncthreads();
    }
    if (t == 0) g_partial[blockIdx.x] = ssum[0];
}

// ---------------------------------------------------------------------------
// Pass 3b: deterministic fixed-order final mean (one thread).
// ---------------------------------------------------------------------------
__global__ void mrr_pass3b(float* __restrict__ out)
{
    if (threadIdx.x == 0) {
        double s = 0.0;
        #pragma unroll
        for (int i = 0; i < P3A_BLOCKS; i++) s += g_partial[i];
        out[0] = (float)(s / (double)N_POS);
    }
}

extern "C" void kernel_launch(void* const* d_in, const int* in_sizes, int n_in,
                              void* d_out, int out_size)
{
    const float* val = (const float*)d_in[0];
    const int*   idx = (const int*)d_in[1];
    float*       out = (float*)d_out;

    mrr_pass1<<<2048, 256>>>(val, idx);
    mrr_pass2<<<P2_BLOCKS, P2_THREADS>>>(val);
    mrr_pass3a<<<P3A_BLOCKS, P3A_THREADS>>>(out);
    mrr_pass3b<<<1, 32>>>(out);
}